// round 7
// baseline (speedup 1.0000x reference)
#include <cuda_runtime.h>
#include <cuda_fp16.h>
#include <cstdint>

#define N_VOX 200000
#define C_CH  128
#define BM    128
#define NTILE ((N_VOX + BM - 1) / BM)   // 1563
#define EPSV  1e-5f

#define NCHUNK 6                         // 384 / 64
#define MATB   16384                     // 128 rows * 128 bytes (64 fp16)
#define BUFB   (2 * MATB)                // A + W = 32768
#define SSUM_OFF (3 * BUFB)              // 98304
#define SM_TOTAL (SSUM_OFF + 1024)       // 99328 -> 2 CTAs/SM

// ---------------------------------------------------------------------------
// Global scratch (no cudaMalloc allowed)
__device__ __align__(16) __half g_xf[(size_t)(N_VOX + 1) * C_CH];
// Wt images: [axis*3+seg][n=128][k=128] fp16 (B^T, k contiguous)
__device__ __align__(16) __half g_wtf[9 * C_CH * C_CH];
__device__ float g_out[(size_t)3 * N_VOX * C_CH];
__device__ float g_sum[3 * C_CH];
__device__ float g_sq [3 * C_CH];
__device__ float g_scale[3 * C_CH];
__device__ float g_shift[3 * C_CH];

// ---------------------------------------------------------------------------
__device__ __forceinline__ uint32_t smem_u32(const void* p) {
    uint32_t a;
    asm("{ .reg .u64 t; cvta.to.shared.u64 t, %1; cvt.u32.u64 %0, t; }"
        : "=r"(a) : "l"(p));
    return a;
}
__device__ __forceinline__ void cp16(uint32_t dst, const void* src) {
    asm volatile("cp.async.cg.shared.global [%0], [%1], 16;"
                 :: "r"(dst), "l"(src));
}
#define CP_COMMIT() asm volatile("cp.async.commit_group;" ::: "memory")
#define CP_WAIT1()  asm volatile("cp.async.wait_group 1;" ::: "memory")
#define CP_WAIT0()  asm volatile("cp.async.wait_group 0;" ::: "memory")

#define LDSM4(R, addr) \
    asm volatile("ldmatrix.sync.aligned.m8n8.x4.shared.b16 {%0,%1,%2,%3}, [%4];" \
        : "=r"((R)[0]), "=r"((R)[1]), "=r"((R)[2]), "=r"((R)[3]) : "r"(addr))

#define MMA16816(D, A, B0, B1) \
    asm volatile("mma.sync.aligned.m16n8k16.row.col.f32.f16.f16.f32 " \
        "{%0,%1,%2,%3}, {%4,%5,%6,%7}, {%8,%9}, {%0,%1,%2,%3};" \
        : "+f"((D)[0]), "+f"((D)[1]), "+f"((D)[2]), "+f"((D)[3]) \
        : "r"((A)[0]), "r"((A)[1]), "r"((A)[2]), "r"((A)[3]), "r"(B0), "r"(B1))

// SW128 swizzle for 128B rows: 8 x 16B chunks, chunk ^= (row & 7)
__device__ __forceinline__ uint32_t swz(int r, int c) {
    return (uint32_t)(r * 128) + (uint32_t)((c ^ (r & 7)) << 4);
}

// ---------------------------------------------------------------------------
__global__ void init_stats_kernel() {
    int t = threadIdx.x;
    if (t < 3 * C_CH) { g_sum[t] = 0.f; g_sq[t] = 0.f; }
}

// fp32 -> fp16 features (+ zero sentinel row N)
__global__ __launch_bounds__(256) void convert_kernel(const float* __restrict__ x)
{
    int i = blockIdx.x * blockDim.x + threadIdx.x;
    const int TOTP = (N_VOX + 1) * C_CH / 2;
    if (i >= TOTP) return;
    int j = i * 2;
    float2 v = (j < N_VOX * C_CH) ? *reinterpret_cast<const float2*>(x + j)
                                  : make_float2(0.f, 0.f);
    __half2 h;
    h.x = __float2half_rn(v.x);
    h.y = __float2half_rn(v.y);
    *reinterpret_cast<__half2*>(g_xf + j) = h;
}

// W[a][s][k][n] -> Wt[a*3+s][n][k] fp16
__global__ __launch_bounds__(256) void wprep_kernel(const float* __restrict__ W)
{
    int gid = blockIdx.x * blockDim.x + threadIdx.x;
    if (gid >= 9 * C_CH * C_CH) return;
    int as = gid >> 14;
    int k  = (gid >> 7) & 127;
    int n  = gid & 127;
    g_wtf[(size_t)as * C_CH * C_CH + (size_t)n * C_CH + k] = __float2half_rn(W[gid]);
}

// ---------------------------------------------------------------------------
__global__ __launch_bounds__(512, 2) void gemm_kernel(const int* __restrict__ nb)
{
    extern __shared__ char smem[];
    const uint32_t sbase = smem_u32(smem);
    const int tid  = threadIdx.x;
    const int lane = tid & 31, wid = tid >> 5;
    const int wm   = wid >> 2, wn = wid & 3;      // 4(m) x 4(n) warp grid
    const int a     = blockIdx.y;
    const int tile0 = blockIdx.x * BM;

    float* ssum = (float*)(smem + SSUM_OFF);
    float* ssq  = ssum + C_CH;
    if (tid < C_CH) { ssum[tid] = 0.f; ssq[tid] = 0.f; }

    // per-thread gather indices (row r = tid>>2), loaded once
    const int r_ld = tid >> 2, c_ld = tid & 3;
    int iSeg[3];
    {
        int row_g = tile0 + r_ld;
        if (row_g >= N_VOX) { iSeg[0] = iSeg[1] = iSeg[2] = N_VOX; }
        else {
            iSeg[0] = nb[(size_t)(a * 2) * N_VOX + row_g];
            iSeg[1] = row_g;
            iSeg[2] = nb[(size_t)(a * 2 + 1) * N_VOX + row_g];
        }
    }
    const char* wbaseA = (const char*)g_wtf + (size_t)(a * 3) * 32768;

    // cp.async one k64 chunk (seg = ch>>1, k-half = ch&1) into buffer ch%3
    auto load_chunk = [&](int ch) {
        const int seg = ch >> 1, kh = ch & 1;
        const char* srcA = (const char*)g_xf + (size_t)iSeg[seg] * 256 + kh * 128;
        const char* srcW = wbaseA + (size_t)seg * 32768 + (size_t)r_ld * 256 + kh * 128;
        const uint32_t bufb = sbase + (uint32_t)(ch % 3) * BUFB;
        #pragma unroll
        for (int j = 0; j < 2; ++j) {
            int c = c_ld + j * 4;                     // 16B chunk 0..7
            uint32_t d = bufb + swz(r_ld, c);
            cp16(d,        srcA + c * 16);
            cp16(d + MATB, srcW + c * 16);
        }
    };

    load_chunk(0); CP_COMMIT();
    load_chunk(1); CP_COMMIT();

    float c[2][4][4];
    #pragma unroll
    for (int i = 0; i < 2; ++i)
        #pragma unroll
        for (int j = 0; j < 4; ++j)
            #pragma unroll
            for (int e = 0; e < 4; ++e) c[i][j][e] = 0.f;

    // fragment row indices / swizzle chunk phase
    int rA[2], rB[2];
    rA[0] = wm * 32 + (lane & 15); rA[1] = rA[0] + 16;
    rB[0] = wn * 32 + ((lane >> 4) << 3) + (lane & 7); rB[1] = rB[0] + 16;
    const int cA = lane >> 4;            // 0/1: which k16 within the k32 pair
    const int cB = (lane >> 3) & 1;

    #pragma unroll 1
    for (int ch = 0; ch < NCHUNK; ++ch) {
        if (ch < NCHUNK - 1) CP_WAIT1(); else CP_WAIT0();
        __syncthreads();                              // data ready + prev stage free
        if (ch + 2 < NCHUNK) { load_chunk(ch + 2); CP_COMMIT(); }
        const uint32_t bufb = sbase + (uint32_t)(ch % 3) * BUFB;

        #pragma unroll
        for (int kk = 0; kk < 4; ++kk) {              // 4 x k16
            uint32_t ah[2][4], bb[2][4];
            #pragma unroll
            for (int ma = 0; ma < 2; ++ma)
                LDSM4(ah[ma], bufb + swz(rA[ma], kk * 2 + cA));
            #pragma unroll
            for (int q = 0; q < 2; ++q)
                LDSM4(bb[q], bufb + MATB + swz(rB[q], kk * 2 + cB));

            #pragma unroll
            for (int q = 0; q < 2; ++q)
                #pragma unroll
                for (int h = 0; h < 2; ++h)
                    #pragma unroll
                    for (int ma = 0; ma < 2; ++ma)
                        MMA16816(c[ma][q * 2 + h], ah[ma],
                                 bb[q][h * 2], bb[q][h * 2 + 1]);
        }
    }

    // ---- epilogue: store pre-BN output + per-channel stats
    float scs[8], scq[8];
    #pragma unroll
    for (int i = 0; i < 8; ++i) { scs[i] = 0.f; scq[i] = 0.f; }

    const int rq = lane >> 2, cq2 = (lane & 3) * 2;
    #pragma unroll
    for (int ma = 0; ma < 2; ++ma) {
        #pragma unroll
        for (int na = 0; na < 4; ++na) {
            float* cc = c[ma][na];
            int r0 = tile0 + wm * 32 + ma * 16 + rq;
            int col = wn * 32 + na * 8 + cq2;
            float* dst = g_out + (size_t)a * N_VOX * C_CH + (size_t)r0 * C_CH + col;
            if (r0 < N_VOX)
                *reinterpret_cast<float2*>(dst) = make_float2(cc[0], cc[1]);
            if (r0 + 8 < N_VOX)
                *reinterpret_cast<float2*>(dst + 8 * C_CH) = make_float2(cc[2], cc[3]);
            scs[na * 2]     += cc[0] + cc[2];
            scs[na * 2 + 1] += cc[1] + cc[3];
            scq[na * 2]     += cc[0] * cc[0] + cc[2] * cc[2];
            scq[na * 2 + 1] += cc[1] * cc[1] + cc[3] * cc[3];
        }
    }
    #pragma unroll
    for (int na = 0; na < 4; ++na) {
        int col = wn * 32 + na * 8 + cq2;
        atomicAdd(&ssum[col],     scs[na * 2]);
        atomicAdd(&ssum[col + 1], scs[na * 2 + 1]);
        atomicAdd(&ssq[col],      scq[na * 2]);
        atomicAdd(&ssq[col + 1],  scq[na * 2 + 1]);
    }
    __syncthreads();
    if (tid < C_CH) {
        atomicAdd(&g_sum[a * C_CH + tid], ssum[tid]);
        atomicAdd(&g_sq [a * C_CH + tid], ssq[tid]);
    }
}

// ---------------------------------------------------------------------------
__global__ void finalize_kernel(const float* __restrict__ gamma,
                                const float* __restrict__ beta)
{
    int t = threadIdx.x;
    if (t >= 3 * C_CH) return;
    float invN = 1.0f / (float)N_VOX;
    float mu  = g_sum[t] * invN;
    float var = g_sq[t] * invN - mu * mu;
    float rs  = rsqrtf(var + EPSV);
    float sc  = rs * gamma[t];
    g_scale[t] = sc;
    g_shift[t] = beta[t] - mu * sc;
}

__global__ __launch_bounds__(256) void final_kernel(
    const float* __restrict__ x, float* __restrict__ out)
{
    int i4 = blockIdx.x * blockDim.x + threadIdx.x;
    const int TOT4 = N_VOX * C_CH / 4;
    if (i4 >= TOT4) return;
    int c = (i4 * 4) & (C_CH - 1);

    float4 xv = reinterpret_cast<const float4*>(x)[i4];
    float r0 = 0.f, r1 = 0.f, r2 = 0.f, r3 = 0.f;
    #pragma unroll
    for (int a = 0; a < 3; ++a) {
        float4 o  = reinterpret_cast<const float4*>(g_out + (size_t)a * N_VOX * C_CH)[i4];
        float4 sc = *reinterpret_cast<const float4*>(&g_scale[a * C_CH + c]);
        float4 sh = *reinterpret_cast<const float4*>(&g_shift[a * C_CH + c]);
        float t0 = o.x * sc.x + sh.x;
        float t1 = o.y * sc.y + sh.y;
        float t2 = o.z * sc.z + sh.z;
        float t3 = o.w * sc.w + sh.w;
        r0 += 1.f / (1.f + __expf(-t0));
        r1 += 1.f / (1.f + __expf(-t1));
        r2 += 1.f / (1.f + __expf(-t2));
        r3 += 1.f / (1.f + __expf(-t3));
    }
    reinterpret_cast<float4*>(out)[i4] =
        make_float4(xv.x * r0, xv.y * r1, xv.z * r2, xv.w * r3);
}

// ---------------------------------------------------------------------------
extern "C" void kernel_launch(void* const* d_in, const int* in_sizes, int n_in,
                              void* d_out, int out_size)
{
    const float* x     = (const float*)d_in[0];   // [N, C]
    const int*   nb    = (const int*)  d_in[1];   // [3, 2, N]
    const float* W     = (const float*)d_in[2];   // [3, 3, C, C]
    const float* gamma = (const float*)d_in[3];   // [3, C]
    const float* beta  = (const float*)d_in[4];   // [3, C]
    float*       out   = (float*)d_out;

    cudaFuncSetAttribute(gemm_kernel,
                         cudaFuncAttributeMaxDynamicSharedMemorySize, SM_TOTAL);

    init_stats_kernel<<<1, 3 * C_CH>>>();
    {
        int totp = (N_VOX + 1) * C_CH / 2;
        convert_kernel<<<(totp + 255) / 256, 256>>>(x);
    }
    wprep_kernel<<<(9 * C_CH * C_CH + 255) / 256, 256>>>(W);
    gemm_kernel<<<dim3(NTILE, 3), 512, SM_TOTAL>>>(nb);
    finalize_kernel<<<1, 3 * C_CH>>>(gamma, beta);
    final_kernel<<<(N_VOX * C_CH / 4 + 255) / 256, 256>>>(x, out);
}

// round 8
// speedup vs baseline: 2.1640x; 2.1640x over previous
#include <cuda_runtime.h>
#include <cuda_fp16.h>
#include <cstdint>

#define N_VOX 200000
#define C_CH  128
#define BM    64
#define NTILE (N_VOX / BM)               // 3125 exact
#define EPSV  1e-5f

#define NCHUNK 6                         // 384 / 64
#define MAT_A  8192                      // 64 rows * 128B
#define MAT_W  16384                     // 128 rows * 128B
#define BUFB   (MAT_A + MAT_W)           // 24576
#define SSUM_OFF (3 * BUFB)              // 73728
#define SM_TOTAL (SSUM_OFF + 1024)       // 74752 -> 3 CTAs/SM

// ---------------------------------------------------------------------------
// Global scratch (no cudaMalloc allowed)
__device__ __align__(16) __half g_xf[(size_t)(N_VOX + 1) * C_CH];
// Wt images: [axis*3+seg][n=128][k=128] fp16 (B^T, k contiguous)
__device__ __align__(16) __half g_wtf[9 * C_CH * C_CH];
__device__ float g_out[(size_t)3 * N_VOX * C_CH];
__device__ float g_sum[3 * C_CH];
__device__ float g_sq [3 * C_CH];
__device__ float g_scale[3 * C_CH];
__device__ float g_shift[3 * C_CH];

// ---------------------------------------------------------------------------
__device__ __forceinline__ uint32_t smem_u32(const void* p) {
    uint32_t a;
    asm("{ .reg .u64 t; cvta.to.shared.u64 t, %1; cvt.u32.u64 %0, t; }"
        : "=r"(a) : "l"(p));
    return a;
}
__device__ __forceinline__ void cp16(uint32_t dst, const void* src) {
    asm volatile("cp.async.cg.shared.global [%0], [%1], 16;"
                 :: "r"(dst), "l"(src));
}
#define CP_COMMIT() asm volatile("cp.async.commit_group;" ::: "memory")
#define CP_WAIT1()  asm volatile("cp.async.wait_group 1;" ::: "memory")
#define CP_WAIT0()  asm volatile("cp.async.wait_group 0;" ::: "memory")

#define LDSM4(R, addr) \
    asm volatile("ldmatrix.sync.aligned.m8n8.x4.shared.b16 {%0,%1,%2,%3}, [%4];" \
        : "=r"((R)[0]), "=r"((R)[1]), "=r"((R)[2]), "=r"((R)[3]) : "r"(addr))

#define MMA16816(D, A, B0, B1) \
    asm volatile("mma.sync.aligned.m16n8k16.row.col.f32.f16.f16.f32 " \
        "{%0,%1,%2,%3}, {%4,%5,%6,%7}, {%8,%9}, {%0,%1,%2,%3};" \
        : "+f"((D)[0]), "+f"((D)[1]), "+f"((D)[2]), "+f"((D)[3]) \
        : "r"((A)[0]), "r"((A)[1]), "r"((A)[2]), "r"((A)[3]), "r"(B0), "r"(B1))

// SW128 swizzle for 128B rows: 8 x 16B chunks, chunk ^= (row & 7)
__device__ __forceinline__ uint32_t swz(int r, int c) {
    return (uint32_t)(r * 128) + (uint32_t)((c ^ (r & 7)) << 4);
}

// ---------------------------------------------------------------------------
__global__ void init_stats_kernel() {
    int t = threadIdx.x;
    if (t < 3 * C_CH) { g_sum[t] = 0.f; g_sq[t] = 0.f; }
}

// fp32 -> fp16 features (+ zero sentinel row N)
__global__ __launch_bounds__(256) void convert_kernel(const float* __restrict__ x)
{
    int i = blockIdx.x * blockDim.x + threadIdx.x;
    const int TOTP = (N_VOX + 1) * C_CH / 2;
    if (i >= TOTP) return;
    int j = i * 2;
    float2 v = (j < N_VOX * C_CH) ? *reinterpret_cast<const float2*>(x + j)
                                  : make_float2(0.f, 0.f);
    __half2 h;
    h.x = __float2half_rn(v.x);
    h.y = __float2half_rn(v.y);
    *reinterpret_cast<__half2*>(g_xf + j) = h;
}

// W[a][s][k][n] -> Wt[a*3+s][n][k] fp16
__global__ __launch_bounds__(256) void wprep_kernel(const float* __restrict__ W)
{
    int gid = blockIdx.x * blockDim.x + threadIdx.x;
    if (gid >= 9 * C_CH * C_CH) return;
    int as = gid >> 14;
    int k  = (gid >> 7) & 127;
    int n  = gid & 127;
    g_wtf[(size_t)as * C_CH * C_CH + (size_t)n * C_CH + k] = __float2half_rn(W[gid]);
}

// ---------------------------------------------------------------------------
__global__ __launch_bounds__(512, 3) void gemm_kernel(const int* __restrict__ nb)
{
    extern __shared__ char smem[];
    const uint32_t sbase = smem_u32(smem);
    const int tid  = threadIdx.x;
    const int lane = tid & 31, wid = tid >> 5;
    const int wm   = wid >> 3, wn = wid & 7;      // 2(m) x 8(n) warp grid
    const int a     = blockIdx.y;
    const int tile0 = blockIdx.x * BM;

    float* ssum = (float*)(smem + SSUM_OFF);
    float* ssq  = ssum + C_CH;
    if (tid < C_CH) { ssum[tid] = 0.f; ssq[tid] = 0.f; }

    // per-thread gather indices for A row r_ld = tid>>3
    const int r_ld = tid >> 3, c_ld = tid & 7;
    int iSeg[3];
    {
        int row_g = tile0 + r_ld;
        iSeg[0] = nb[(size_t)(a * 2) * N_VOX + row_g];
        iSeg[1] = row_g;
        iSeg[2] = nb[(size_t)(a * 2 + 1) * N_VOX + row_g];
    }
    const char* wbaseA = (const char*)g_wtf + (size_t)(a * 3) * 32768;

    // cp.async one k64 chunk (seg = ch>>1, k-half = ch&1) into buffer ch%3
    auto load_chunk = [&](int ch) {
        const int seg = ch >> 1, kh = ch & 1;
        const char* srcA = (const char*)g_xf + (size_t)iSeg[seg] * 256 + kh * 128;
        const char* wseg = wbaseA + (size_t)seg * 32768 + kh * 128;
        const uint32_t bufb = sbase + (uint32_t)(ch % 3) * BUFB;
        cp16(bufb + swz(r_ld, c_ld), srcA + c_ld * 16);
        cp16(bufb + MAT_A + swz(r_ld, c_ld),
             wseg + (size_t)r_ld * 256 + c_ld * 16);
        cp16(bufb + MAT_A + swz(r_ld + 64, c_ld),
             wseg + (size_t)(r_ld + 64) * 256 + c_ld * 16);
    };

    load_chunk(0); CP_COMMIT();
    load_chunk(1); CP_COMMIT();

    float c[2][2][4];
    #pragma unroll
    for (int i = 0; i < 2; ++i)
        #pragma unroll
        for (int j = 0; j < 2; ++j)
            #pragma unroll
            for (int e = 0; e < 4; ++e) c[i][j][e] = 0.f;

    // fragment row indices / swizzle chunk phase
    int rA[2];
    rA[0] = wm * 32 + (lane & 15); rA[1] = rA[0] + 16;
    const int rB = wn * 16 + ((lane >> 4) << 3) + (lane & 7);
    const int cA = lane >> 4;
    const int cB = (lane >> 3) & 1;

    #pragma unroll 1
    for (int ch = 0; ch < NCHUNK; ++ch) {
        if (ch < NCHUNK - 1) CP_WAIT1(); else CP_WAIT0();
        __syncthreads();                              // data ready + prev stage free
        if (ch + 2 < NCHUNK) { load_chunk(ch + 2); CP_COMMIT(); }
        const uint32_t bufb = sbase + (uint32_t)(ch % 3) * BUFB;

        #pragma unroll
        for (int kk = 0; kk < 4; ++kk) {              // 4 x k16
            uint32_t ah[2][4], bb[4];
            #pragma unroll
            for (int ma = 0; ma < 2; ++ma)
                LDSM4(ah[ma], bufb + swz(rA[ma], kk * 2 + cA));
            LDSM4(bb, bufb + MAT_A + swz(rB, kk * 2 + cB));

            #pragma unroll
            for (int h = 0; h < 2; ++h)
                #pragma unroll
                for (int ma = 0; ma < 2; ++ma)
                    MMA16816(c[ma][h], ah[ma], bb[h * 2], bb[h * 2 + 1]);
        }
    }

    // ---- epilogue: store pre-BN output + per-channel stats
    float scs[4], scq[4];
    #pragma unroll
    for (int i = 0; i < 4; ++i) { scs[i] = 0.f; scq[i] = 0.f; }

    const int rq = lane >> 2, cq2 = (lane & 3) * 2;
    #pragma unroll
    for (int ma = 0; ma < 2; ++ma) {
        #pragma unroll
        for (int na = 0; na < 2; ++na) {
            float* cc = c[ma][na];
            int r0 = tile0 + wm * 32 + ma * 16 + rq;
            int col = wn * 16 + na * 8 + cq2;
            float* dst = g_out + (size_t)a * N_VOX * C_CH + (size_t)r0 * C_CH + col;
            *reinterpret_cast<float2*>(dst) = make_float2(cc[0], cc[1]);
            *reinterpret_cast<float2*>(dst + 8 * C_CH) = make_float2(cc[2], cc[3]);
            scs[na * 2]     += cc[0] + cc[2];
            scs[na * 2 + 1] += cc[1] + cc[3];
            scq[na * 2]     += cc[0] * cc[0] + cc[2] * cc[2];
            scq[na * 2 + 1] += cc[1] * cc[1] + cc[3] * cc[3];
        }
    }
    #pragma unroll
    for (int na = 0; na < 2; ++na) {
        int col = wn * 16 + na * 8 + cq2;
        atomicAdd(&ssum[col],     scs[na * 2]);
        atomicAdd(&ssum[col + 1], scs[na * 2 + 1]);
        atomicAdd(&ssq[col],      scq[na * 2]);
        atomicAdd(&ssq[col + 1],  scq[na * 2 + 1]);
    }
    __syncthreads();
    if (tid < C_CH) {
        atomicAdd(&g_sum[a * C_CH + tid], ssum[tid]);
        atomicAdd(&g_sq [a * C_CH + tid], ssq[tid]);
    }
}

// ---------------------------------------------------------------------------
__global__ void finalize_kernel(const float* __restrict__ gamma,
                                const float* __restrict__ beta)
{
    int t = threadIdx.x;
    if (t >= 3 * C_CH) return;
    float invN = 1.0f / (float)N_VOX;
    float mu  = g_sum[t] * invN;
    float var = g_sq[t] * invN - mu * mu;
    float rs  = rsqrtf(var + EPSV);
    float sc  = rs * gamma[t];
    g_scale[t] = sc;
    g_shift[t] = beta[t] - mu * sc;
}

__global__ __launch_bounds__(256) void final_kernel(
    const float* __restrict__ x, float* __restrict__ out)
{
    int i4 = blockIdx.x * blockDim.x + threadIdx.x;
    const int TOT4 = N_VOX * C_CH / 4;
    if (i4 >= TOT4) return;
    int c = (i4 * 4) & (C_CH - 1);

    float4 xv = reinterpret_cast<const float4*>(x)[i4];
    float r0 = 0.f, r1 = 0.f, r2 = 0.f, r3 = 0.f;
    #pragma unroll
    for (int a = 0; a < 3; ++a) {
        float4 o  = reinterpret_cast<const float4*>(g_out + (size_t)a * N_VOX * C_CH)[i4];
        float4 sc = *reinterpret_cast<const float4*>(&g_scale[a * C_CH + c]);
        float4 sh = *reinterpret_cast<const float4*>(&g_shift[a * C_CH + c]);
        float t0 = o.x * sc.x + sh.x;
        float t1 = o.y * sc.y + sh.y;
        float t2 = o.z * sc.z + sh.z;
        float t3 = o.w * sc.w + sh.w;
        r0 += 1.f / (1.f + __expf(-t0));
        r1 += 1.f / (1.f + __expf(-t1));
        r2 += 1.f / (1.f + __expf(-t2));
        r3 += 1.f / (1.f + __expf(-t3));
    }
    reinterpret_cast<float4*>(out)[i4] =
        make_float4(xv.x * r0, xv.y * r1, xv.z * r2, xv.w * r3);
}

// ---------------------------------------------------------------------------
extern "C" void kernel_launch(void* const* d_in, const int* in_sizes, int n_in,
                              void* d_out, int out_size)
{
    const float* x     = (const float*)d_in[0];   // [N, C]
    const int*   nb    = (const int*)  d_in[1];   // [3, 2, N]
    const float* W     = (const float*)d_in[2];   // [3, 3, C, C]
    const float* gamma = (const float*)d_in[3];   // [3, C]
    const float* beta  = (const float*)d_in[4];   // [3, C]
    float*       out   = (float*)d_out;

    cudaFuncSetAttribute(gemm_kernel,
                         cudaFuncAttributeMaxDynamicSharedMemorySize, SM_TOTAL);

    init_stats_kernel<<<1, 3 * C_CH>>>();
    {
        int totp = (N_VOX + 1) * C_CH / 2;
        convert_kernel<<<(totp + 255) / 256, 256>>>(x);
    }
    wprep_kernel<<<(9 * C_CH * C_CH + 255) / 256, 256>>>(W);
    gemm_kernel<<<dim3(NTILE, 3), 512, SM_TOTAL>>>(nb);
    finalize_kernel<<<1, 3 * C_CH>>>(gamma, beta);
    final_kernel<<<(N_VOX * C_CH / 4 + 255) / 256, 256>>>(x, out);
}